// round 16
// baseline (speedup 1.0000x reference)
#include <cuda_runtime.h>

// ---------------------------------------------------------------------------
// Problem constants
// ---------------------------------------------------------------------------
#define B_   2
#define L_   2048
#define C_   1024
#define H_   16
#define D_   64
#define MTOT 4096
#define Y_ELEMS ((size_t)MTOT * C_)                 // 4,194,304
#define ATTN_ELEMS ((size_t)B_ * H_ * L_ * L_)      // 134,217,728
#define INV_SCALE 0.022097086912079612f             // 1/sqrt(2048)

// ---------------------------------------------------------------------------
// Scratch (device globals)
// ---------------------------------------------------------------------------
__device__ float g_QH[B_ * H_ * L_ * D_];
__device__ float g_KH[B_ * H_ * L_ * D_];
__device__ float g_VH[B_ * H_ * L_ * D_];
__device__ float g_YH[Y_ELEMS];
__device__ float g_RSinv[B_ * H_ * L_];

// ---------------------------------------------------------------------------
// tf32 helpers
// ---------------------------------------------------------------------------
__device__ __forceinline__ unsigned f2t(float f) {
    unsigned u;
    asm("cvt.rna.tf32.f32 %0, %1;" : "=r"(u) : "f"(f));
    return u;
}
__device__ __forceinline__ float f2tf(float f) { return __uint_as_float(f2t(f)); }

__device__ __forceinline__ void mma8(float* c,
                                     unsigned a0, unsigned a1, unsigned a2, unsigned a3,
                                     unsigned b0, unsigned b1) {
    asm volatile(
        "mma.sync.aligned.m16n8k8.row.col.f32.tf32.tf32.f32 "
        "{%0,%1,%2,%3}, {%4,%5,%6,%7}, {%8,%9}, {%0,%1,%2,%3};"
        : "+f"(c[0]), "+f"(c[1]), "+f"(c[2]), "+f"(c[3])
        : "r"(a0), "r"(a1), "r"(a2), "r"(a3), "r"(b0), "r"(b1));
}

// ---------------------------------------------------------------------------
// tf32 NT GEMM:  out(M x N) = X(M x K) @ W(N x K)^T,  M=4096, N=1024, K=1024
// 128x128 tile, BK=32, 256 threads (8 warps, 2x4), warp tile 64x32.
// ---------------------------------------------------------------------------
__global__ __launch_bounds__(256, 2)
void gemm_tf32(const float* __restrict__ X, const float* __restrict__ W,
               float* __restrict__ out, int scatter)
{
    __shared__ float Xs[128 * 36];
    __shared__ float Ws[128 * 36];

    const int t = threadIdx.x;
    const int lane = t & 31, wid = t >> 5;
    const int lq = lane >> 2, lr = lane & 3;
    const int wm = wid & 1, wn = wid >> 1;

    const float* Xg = X + (size_t)(blockIdx.y * 128) * 1024;
    const float* Wg = W + (size_t)(blockIdx.x * 128) * 1024;

    float acc[4][4][4];
#pragma unroll
    for (int i = 0; i < 4; i++)
#pragma unroll
        for (int j = 0; j < 4; j++)
#pragma unroll
            for (int k = 0; k < 4; k++) acc[i][j][k] = 0.0f;

    for (int k0 = 0; k0 < 1024; k0 += 32) {
        float4 xr[4], wr[4];
#pragma unroll
        for (int i = 0; i < 4; i++) {
            const int f4 = i * 256 + t;
            const int row = f4 >> 3, c4 = (f4 & 7) << 2;
            xr[i] = *(const float4*)(Xg + (size_t)row * 1024 + k0 + c4);
            wr[i] = *(const float4*)(Wg + (size_t)row * 1024 + k0 + c4);
        }
        __syncthreads();
#pragma unroll
        for (int i = 0; i < 4; i++) {
            const int f4 = i * 256 + t;
            const int row = f4 >> 3, c4 = (f4 & 7) << 2;
            *(float4*)(Xs + row * 36 + c4) =
                make_float4(f2tf(xr[i].x), f2tf(xr[i].y), f2tf(xr[i].z), f2tf(xr[i].w));
            *(float4*)(Ws + row * 36 + c4) =
                make_float4(f2tf(wr[i].x), f2tf(wr[i].y), f2tf(wr[i].z), f2tf(wr[i].w));
        }
        __syncthreads();

#pragma unroll
        for (int kk = 0; kk < 4; kk++) {
            const int k = kk * 8;
            unsigned a[4][4];
#pragma unroll
            for (int mt = 0; mt < 4; mt++) {
                const int r0 = wm * 64 + mt * 16 + lq;
                a[mt][0] = __float_as_uint(Xs[r0 * 36 + k + lr]);
                a[mt][1] = __float_as_uint(Xs[(r0 + 8) * 36 + k + lr]);
                a[mt][2] = __float_as_uint(Xs[r0 * 36 + k + 4 + lr]);
                a[mt][3] = __float_as_uint(Xs[(r0 + 8) * 36 + k + 4 + lr]);
            }
#pragma unroll
            for (int nt = 0; nt < 4; nt++) {
                const int nc = wn * 32 + nt * 8 + lq;
                const unsigned b0 = __float_as_uint(Ws[nc * 36 + k + lr]);
                const unsigned b1 = __float_as_uint(Ws[nc * 36 + k + 4 + lr]);
#pragma unroll
                for (int mt = 0; mt < 4; mt++)
                    mma8(acc[mt][nt], a[mt][0], a[mt][1], a[mt][2], a[mt][3], b0, b1);
            }
        }
    }

    // epilogue: c0,c1 -> (m, n..n+1); c2,c3 -> (m+8, n..n+1)
#pragma unroll
    for (int mt = 0; mt < 4; mt++) {
#pragma unroll
        for (int nt = 0; nt < 4; nt++) {
            const int m = blockIdx.y * 128 + wm * 64 + mt * 16 + lq;
            const int n = blockIdx.x * 128 + wn * 32 + nt * 8 + 2 * lr;
            const float2 v0 = make_float2(acc[mt][nt][0], acc[mt][nt][1]);
            const float2 v1 = make_float2(acc[mt][nt][2], acc[mt][nt][3]);
            if (scatter) {
                const int h = n >> 6, d = n & 63;
                const int bb = m >> 11, l = m & 2047;
                *(float2*)(out + ((size_t)((bb * H_ + h) * L_ + l)) * D_ + d) = v0;
                *(float2*)(out + ((size_t)((bb * H_ + h) * L_ + l + 8)) * D_ + d) = v1;
            } else {
                *(float2*)(out + (size_t)m * 1024 + n) = v0;
                *(float2*)(out + (size_t)(m + 8) * 1024 + n) = v1;
            }
        }
    }
}

// ---------------------------------------------------------------------------
// Tensor-core attention: per (b,h) x 128-query tile. 256 threads / 8 warps.
// S phase: warp tile 32(m) x 64(n); PV phase: warp tile 16(m) x 64(d).
// smem floats: Qs[128*68] Ks[128*68] Vs[128*68] Ps[128*132] red[256] rsi[128]
// ---------------------------------------------------------------------------
#define AT_QS   0
#define AT_KS   8704
#define AT_VS   17408
#define AT_PS   26112
#define AT_RED  43008
#define AT_RSI  43264
#define AT_FLOATS 43392
#define AT_BYTES (AT_FLOATS * 4)

__global__ __launch_bounds__(256, 1)
void attn_tc(float* __restrict__ attn_out)
{
    extern __shared__ float sm[];
    float* Qs = sm + AT_QS;
    float* Ks = sm + AT_KS;
    float* Vs = sm + AT_VS;
    float* Ps = sm + AT_PS;
    float* red = sm + AT_RED;
    float* rsi = sm + AT_RSI;

    const int t = threadIdx.x;
    const int lane = t & 31, wid = t >> 5;
    const int lq = lane >> 2, lr = lane & 3;
    const int wm = wid & 3, wn = wid >> 2;     // S phase: 4x2 warp grid
    const int bh = blockIdx.y, qt = blockIdx.x;

    const float* Qg = g_QH + (size_t)(bh * L_ + qt * 128) * D_;
    const float* Kg = g_KH + (size_t)bh * L_ * D_;
    const float* Vg = g_VH + (size_t)bh * L_ * D_;
    float* attn_base = attn_out + (size_t)(bh * L_ + qt * 128) * L_;

    // Q tile -> smem (tf32-rounded)
#pragma unroll
    for (int i = 0; i < 8; i++) {
        const int f4 = i * 256 + t;
        const int row = f4 >> 4, c4 = (f4 & 15) << 2;
        float4 v = *(const float4*)(Qg + row * 64 + c4);
        *(float4*)(Qs + row * 68 + c4) =
            make_float4(f2tf(v.x), f2tf(v.y), f2tf(v.z), f2tf(v.w));
    }

    float accY[8][4];
#pragma unroll
    for (int i = 0; i < 8; i++)
#pragma unroll
        for (int j = 0; j < 4; j++) accY[i][j] = 0.0f;
    float rs[4] = {0.f, 0.f, 0.f, 0.f};

    for (int kt = 0; kt < 16; kt++) {
        __syncthreads();   // previous Ks/Vs/Ps consumers done
#pragma unroll
        for (int i = 0; i < 8; i++) {
            const int f4 = i * 256 + t;
            const int row = f4 >> 4, c4 = (f4 & 15) << 2;
            float4 kv = *(const float4*)(Kg + (size_t)(kt * 128 + row) * 64 + c4);
            float4 vv = *(const float4*)(Vg + (size_t)(kt * 128 + row) * 64 + c4);
            *(float4*)(Ks + row * 68 + c4) =
                make_float4(f2tf(kv.x), f2tf(kv.y), f2tf(kv.z), f2tf(kv.w));
            *(float4*)(Vs + row * 68 + c4) =
                make_float4(f2tf(vv.x), f2tf(vv.y), f2tf(vv.z), f2tf(vv.w));
        }
        __syncthreads();

        // ---- S = Q K^T : 2 m-tiles x 8 n-tiles, k=64 ----
        float acc[2][8][4];
#pragma unroll
        for (int i = 0; i < 2; i++)
#pragma unroll
            for (int j = 0; j < 8; j++)
#pragma unroll
                for (int kq = 0; kq < 4; kq++) acc[i][j][kq] = 0.0f;

#pragma unroll
        for (int kk = 0; kk < 8; kk++) {
            const int k = kk * 8;
            unsigned a[2][4];
#pragma unroll
            for (int mt = 0; mt < 2; mt++) {
                const int r0 = wm * 32 + mt * 16 + lq;
                a[mt][0] = __float_as_uint(Qs[r0 * 68 + k + lr]);
                a[mt][1] = __float_as_uint(Qs[(r0 + 8) * 68 + k + lr]);
                a[mt][2] = __float_as_uint(Qs[r0 * 68 + k + 4 + lr]);
                a[mt][3] = __float_as_uint(Qs[(r0 + 8) * 68 + k + 4 + lr]);
            }
#pragma unroll
            for (int nt = 0; nt < 8; nt++) {
                const int nc = wn * 64 + nt * 8 + lq;
                const unsigned b0 = __float_as_uint(Ks[nc * 68 + k + lr]);
                const unsigned b1 = __float_as_uint(Ks[nc * 68 + k + 4 + lr]);
                mma8(acc[0][nt], a[0][0], a[0][1], a[0][2], a[0][3], b0, b1);
                mma8(acc[1][nt], a[1][0], a[1][1], a[1][2], a[1][3], b0, b1);
            }
        }

        // ---- exp, rowsum, write unnormalized attn + stage P ----
#pragma unroll
        for (int mt = 0; mt < 2; mt++) {
            const int r0 = wm * 32 + mt * 16 + lq;
#pragma unroll
            for (int nt = 0; nt < 8; nt++) {
                const float p0 = __expf(acc[mt][nt][0] * INV_SCALE);
                const float p1 = __expf(acc[mt][nt][1] * INV_SCALE);
                const float p2 = __expf(acc[mt][nt][2] * INV_SCALE);
                const float p3 = __expf(acc[mt][nt][3] * INV_SCALE);
                rs[mt * 2 + 0] += p0 + p1;
                rs[mt * 2 + 1] += p2 + p3;
                const int col = wn * 64 + nt * 8 + 2 * lr;
                *(float2*)(attn_base + (size_t)r0 * L_ + kt * 128 + col) =
                    make_float2(p0, p1);
                *(float2*)(attn_base + (size_t)(r0 + 8) * L_ + kt * 128 + col) =
                    make_float2(p2, p3);
                *(float2*)(Ps + r0 * 132 + col) = make_float2(f2tf(p0), f2tf(p1));
                *(float2*)(Ps + (r0 + 8) * 132 + col) = make_float2(f2tf(p2), f2tf(p3));
            }
        }
        __syncthreads();

        // ---- Y += P V : warp w owns rows [16w,16w+16), k over 128 keys ----
#pragma unroll
        for (int ks = 0; ks < 16; ks++) {
            const int k = ks * 8;
            const int r0 = wid * 16 + lq;
            const unsigned a0 = __float_as_uint(Ps[r0 * 132 + k + lr]);
            const unsigned a1 = __float_as_uint(Ps[(r0 + 8) * 132 + k + lr]);
            const unsigned a2 = __float_as_uint(Ps[r0 * 132 + k + 4 + lr]);
            const unsigned a3 = __float_as_uint(Ps[(r0 + 8) * 132 + k + 4 + lr]);
#pragma unroll
            for (int nt = 0; nt < 8; nt++) {
                const int d = nt * 8 + lq;
                const unsigned b0 = __float_as_uint(Vs[(k + lr) * 68 + d]);
                const unsigned b1 = __float_as_uint(Vs[(k + 4 + lr) * 68 + d]);
                mma8(accY[nt], a0, a1, a2, a3, b0, b1);
            }
        }
    }

    // ---- row sums: reduce over quad (lane&3), combine col-halves ----
#pragma unroll
    for (int i = 0; i < 4; i++) {
        rs[i] += __shfl_xor_sync(0xffffffff, rs[i], 1);
        rs[i] += __shfl_xor_sync(0xffffffff, rs[i], 2);
    }
    if (lr == 0) {
#pragma unroll
        for (int i = 0; i < 4; i++) {
            const int row = wm * 32 + (i >> 1) * 16 + (i & 1) * 8 + lq;
            red[wn * 128 + row] = rs[i];
        }
    }
    __syncthreads();
    if (t < 128) {
        const float inv = 1.0f / (red[t] + red[128 + t]);
        rsi[t] = inv;
        g_RSinv[bh * L_ + qt * 128 + t] = inv;
    }
    __syncthreads();

    // ---- normalize Y, store concatenated-head layout ----
    {
        const int b = bh >> 4, h = bh & 15;
        const int r0 = wid * 16 + lq;
        const float inv0 = rsi[r0], inv1 = rsi[r0 + 8];
        const int grow0 = b * L_ + qt * 128 + r0;
#pragma unroll
        for (int nt = 0; nt < 8; nt++) {
            const int d = nt * 8 + 2 * lr;
            *(float2*)(g_YH + (size_t)grow0 * C_ + h * 64 + d) =
                make_float2(accY[nt][0] * inv0, accY[nt][1] * inv0);
            *(float2*)(g_YH + (size_t)(grow0 + 8) * C_ + h * 64 + d) =
                make_float2(accY[nt][2] * inv1, accY[nt][3] * inv1);
        }
    }
}

// ---------------------------------------------------------------------------
// Normalize attn in place: attn *= 1/rowsum
// ---------------------------------------------------------------------------
__global__ void attn_norm(float4* __restrict__ attn, const float* __restrict__ rsi)
{
    size_t i = (size_t)blockIdx.x * blockDim.x + threadIdx.x;
    const float r = rsi[i >> 9];
    float4 v = attn[i];
    v.x *= r; v.y *= r; v.z *= r; v.w *= r;
    attn[i] = v;
}

// ---------------------------------------------------------------------------
// kernel_launch
// ---------------------------------------------------------------------------
extern "C" void kernel_launch(void* const* d_in, const int* in_sizes, int n_in,
                              void* d_out, int out_size)
{
    const float* q    = (const float*)d_in[0];
    const float* k    = (const float*)d_in[1];
    const float* v    = (const float*)d_in[2];
    const float* w_q  = (const float*)d_in[3];
    const float* w_k  = (const float*)d_in[4];
    const float* w_v  = (const float*)d_in[5];
    const float* fc_y = (const float*)d_in[6];

    float* y_out    = (float*)d_out;
    float* attn_out = y_out + Y_ELEMS;

    float *pQH, *pKH, *pVH, *pYH, *pRS;
    cudaGetSymbolAddress((void**)&pQH, g_QH);
    cudaGetSymbolAddress((void**)&pKH, g_KH);
    cudaGetSymbolAddress((void**)&pVH, g_VH);
    cudaGetSymbolAddress((void**)&pYH, g_YH);
    cudaGetSymbolAddress((void**)&pRS, g_RSinv);

    dim3 gGemm(C_ / 128, MTOT / 128);   // (8, 32)
    dim3 blk(256);

    // Projections -> head-major scratch (tf32 tensor cores)
    gemm_tf32<<<gGemm, blk>>>(q, w_q, pQH, 1);
    gemm_tf32<<<gGemm, blk>>>(k, w_k, pKH, 1);
    gemm_tf32<<<gGemm, blk>>>(v, w_v, pVH, 1);

    // Fused attention (unnormalized attn write + normalized Y)
    cudaFuncSetAttribute(attn_tc, cudaFuncAttributeMaxDynamicSharedMemorySize,
                         AT_BYTES);
    attn_tc<<<dim3(L_ / 128, B_ * H_), blk, AT_BYTES>>>(attn_out);

    // Normalize attn in place
    attn_norm<<<(unsigned)(ATTN_ELEMS / 4 / 256), 256>>>((float4*)attn_out, pRS);

    // y = Y @ fc_y^T
    gemm_tf32<<<gGemm, blk>>>(pYH, fc_y, y_out, 0);
}

// round 17
// speedup vs baseline: 1.0014x; 1.0014x over previous
#include <cuda_runtime.h>

// ---------------------------------------------------------------------------
// Problem constants
// ---------------------------------------------------------------------------
#define B_   2
#define L_   2048
#define C_   1024
#define H_   16
#define D_   64
#define MTOT 4096
#define Y_ELEMS ((size_t)MTOT * C_)                 // 4,194,304
#define ATTN_ELEMS ((size_t)B_ * H_ * L_ * L_)      // 134,217,728
#define INV_SCALE 0.022097086912079612f             // 1/sqrt(2048)

// ---------------------------------------------------------------------------
// Scratch (device globals)
// ---------------------------------------------------------------------------
__device__ float g_QH[B_ * H_ * L_ * D_];
__device__ float g_KH[B_ * H_ * L_ * D_];
__device__ float g_VH[B_ * H_ * L_ * D_];
__device__ float g_YH[Y_ELEMS];
__device__ float g_RSinv[B_ * H_ * L_];

// ---------------------------------------------------------------------------
// tf32 helpers
// ---------------------------------------------------------------------------
__device__ __forceinline__ unsigned f2t(float f) {
    unsigned u;
    asm("cvt.rna.tf32.f32 %0, %1;" : "=r"(u) : "f"(f));
    return u;
}
__device__ __forceinline__ float f2tf(float f) { return __uint_as_float(f2t(f)); }

__device__ __forceinline__ void mma8(float* c,
                                     unsigned a0, unsigned a1, unsigned a2, unsigned a3,
                                     unsigned b0, unsigned b1) {
    asm volatile(
        "mma.sync.aligned.m16n8k8.row.col.f32.tf32.tf32.f32 "
        "{%0,%1,%2,%3}, {%4,%5,%6,%7}, {%8,%9}, {%0,%1,%2,%3};"
        : "+f"(c[0]), "+f"(c[1]), "+f"(c[2]), "+f"(c[3])
        : "r"(a0), "r"(a1), "r"(a2), "r"(a3), "r"(b0), "r"(b1));
}

// ---------------------------------------------------------------------------
// tf32 NT GEMM:  out(M x N) = X(M x K) @ W(N x K)^T,  M=4096, N=1024, K=1024
// 128x128 tile, BK=32, 256 threads (8 warps, 2x4), warp tile 64x32.
// ---------------------------------------------------------------------------
__global__ __launch_bounds__(256, 2)
void gemm_tf32(const float* __restrict__ X, const float* __restrict__ W,
               float* __restrict__ out, int scatter)
{
    __shared__ float Xs[128 * 36];
    __shared__ float Ws[128 * 36];

    const int t = threadIdx.x;
    const int lane = t & 31, wid = t >> 5;
    const int lq = lane >> 2, lr = lane & 3;
    const int wm = wid & 1, wn = wid >> 1;

    const float* Xg = X + (size_t)(blockIdx.y * 128) * 1024;
    const float* Wg = W + (size_t)(blockIdx.x * 128) * 1024;

    float acc[4][4][4];
#pragma unroll
    for (int i = 0; i < 4; i++)
#pragma unroll
        for (int j = 0; j < 4; j++)
#pragma unroll
            for (int k = 0; k < 4; k++) acc[i][j][k] = 0.0f;

    for (int k0 = 0; k0 < 1024; k0 += 32) {
        float4 xr[4], wr[4];
#pragma unroll
        for (int i = 0; i < 4; i++) {
            const int f4 = i * 256 + t;
            const int row = f4 >> 3, c4 = (f4 & 7) << 2;
            xr[i] = *(const float4*)(Xg + (size_t)row * 1024 + k0 + c4);
            wr[i] = *(const float4*)(Wg + (size_t)row * 1024 + k0 + c4);
        }
        __syncthreads();
#pragma unroll
        for (int i = 0; i < 4; i++) {
            const int f4 = i * 256 + t;
            const int row = f4 >> 3, c4 = (f4 & 7) << 2;
            *(float4*)(Xs + row * 36 + c4) =
                make_float4(f2tf(xr[i].x), f2tf(xr[i].y), f2tf(xr[i].z), f2tf(xr[i].w));
            *(float4*)(Ws + row * 36 + c4) =
                make_float4(f2tf(wr[i].x), f2tf(wr[i].y), f2tf(wr[i].z), f2tf(wr[i].w));
        }
        __syncthreads();

#pragma unroll
        for (int kk = 0; kk < 4; kk++) {
            const int k = kk * 8;
            unsigned a[4][4];
#pragma unroll
            for (int mt = 0; mt < 4; mt++) {
                const int r0 = wm * 64 + mt * 16 + lq;
                a[mt][0] = __float_as_uint(Xs[r0 * 36 + k + lr]);
                a[mt][1] = __float_as_uint(Xs[(r0 + 8) * 36 + k + lr]);
                a[mt][2] = __float_as_uint(Xs[r0 * 36 + k + 4 + lr]);
                a[mt][3] = __float_as_uint(Xs[(r0 + 8) * 36 + k + 4 + lr]);
            }
#pragma unroll
            for (int nt = 0; nt < 4; nt++) {
                const int nc = wn * 32 + nt * 8 + lq;
                const unsigned b0 = __float_as_uint(Ws[nc * 36 + k + lr]);
                const unsigned b1 = __float_as_uint(Ws[nc * 36 + k + 4 + lr]);
#pragma unroll
                for (int mt = 0; mt < 4; mt++)
                    mma8(acc[mt][nt], a[mt][0], a[mt][1], a[mt][2], a[mt][3], b0, b1);
            }
        }
    }

    // epilogue: c0,c1 -> (m, n..n+1); c2,c3 -> (m+8, n..n+1)
#pragma unroll
    for (int mt = 0; mt < 4; mt++) {
#pragma unroll
        for (int nt = 0; nt < 4; nt++) {
            const int m = blockIdx.y * 128 + wm * 64 + mt * 16 + lq;
            const int n = blockIdx.x * 128 + wn * 32 + nt * 8 + 2 * lr;
            const float2 v0 = make_float2(acc[mt][nt][0], acc[mt][nt][1]);
            const float2 v1 = make_float2(acc[mt][nt][2], acc[mt][nt][3]);
            if (scatter) {
                const int h = n >> 6, d = n & 63;
                const int bb = m >> 11, l = m & 2047;
                *(float2*)(out + ((size_t)((bb * H_ + h) * L_ + l)) * D_ + d) = v0;
                *(float2*)(out + ((size_t)((bb * H_ + h) * L_ + l + 8)) * D_ + d) = v1;
            } else {
                *(float2*)(out + (size_t)m * 1024 + n) = v0;
                *(float2*)(out + (size_t)(m + 8) * 1024 + n) = v1;
            }
        }
    }
}

// ---------------------------------------------------------------------------
// Tensor-core attention: per (b,h) x 128-query tile. 256 threads / 8 warps.
// S phase: warp tile 32(m) x 64(n); PV phase: warp tile 16(m) x 64(d).
// smem floats: Qs[128*68] Ks[128*68] Vs[128*68] Ps[128*132] red[256] rsi[128]
// ---------------------------------------------------------------------------
#define AT_QS   0
#define AT_KS   8704
#define AT_VS   17408
#define AT_PS   26112
#define AT_RED  43008
#define AT_RSI  43264
#define AT_FLOATS 43392
#define AT_BYTES (AT_FLOATS * 4)

__global__ __launch_bounds__(256, 1)
void attn_tc(float* __restrict__ attn_out)
{
    extern __shared__ float sm[];
    float* Qs = sm + AT_QS;
    float* Ks = sm + AT_KS;
    float* Vs = sm + AT_VS;
    float* Ps = sm + AT_PS;
    float* red = sm + AT_RED;
    float* rsi = sm + AT_RSI;

    const int t = threadIdx.x;
    const int lane = t & 31, wid = t >> 5;
    const int lq = lane >> 2, lr = lane & 3;
    const int wm = wid & 3, wn = wid >> 2;     // S phase: 4x2 warp grid
    const int bh = blockIdx.y, qt = blockIdx.x;

    const float* Qg = g_QH + (size_t)(bh * L_ + qt * 128) * D_;
    const float* Kg = g_KH + (size_t)bh * L_ * D_;
    const float* Vg = g_VH + (size_t)bh * L_ * D_;
    float* attn_base = attn_out + (size_t)(bh * L_ + qt * 128) * L_;

    // Q tile -> smem (tf32-rounded)
#pragma unroll
    for (int i = 0; i < 8; i++) {
        const int f4 = i * 256 + t;
        const int row = f4 >> 4, c4 = (f4 & 15) << 2;
        float4 v = *(const float4*)(Qg + row * 64 + c4);
        *(float4*)(Qs + row * 68 + c4) =
            make_float4(f2tf(v.x), f2tf(v.y), f2tf(v.z), f2tf(v.w));
    }

    float accY[8][4];
#pragma unroll
    for (int i = 0; i < 8; i++)
#pragma unroll
        for (int j = 0; j < 4; j++) accY[i][j] = 0.0f;
    float rs[4] = {0.f, 0.f, 0.f, 0.f};

    for (int kt = 0; kt < 16; kt++) {
        __syncthreads();   // previous Ks/Vs/Ps consumers done
#pragma unroll
        for (int i = 0; i < 8; i++) {
            const int f4 = i * 256 + t;
            const int row = f4 >> 4, c4 = (f4 & 15) << 2;
            float4 kv = *(const float4*)(Kg + (size_t)(kt * 128 + row) * 64 + c4);
            float4 vv = *(const float4*)(Vg + (size_t)(kt * 128 + row) * 64 + c4);
            *(float4*)(Ks + row * 68 + c4) =
                make_float4(f2tf(kv.x), f2tf(kv.y), f2tf(kv.z), f2tf(kv.w));
            *(float4*)(Vs + row * 68 + c4) =
                make_float4(f2tf(vv.x), f2tf(vv.y), f2tf(vv.z), f2tf(vv.w));
        }
        __syncthreads();

        // ---- S = Q K^T : 2 m-tiles x 8 n-tiles, k=64 ----
        float acc[2][8][4];
#pragma unroll
        for (int i = 0; i < 2; i++)
#pragma unroll
            for (int j = 0; j < 8; j++)
#pragma unroll
                for (int kq = 0; kq < 4; kq++) acc[i][j][kq] = 0.0f;

#pragma unroll
        for (int kk = 0; kk < 8; kk++) {
            const int k = kk * 8;
            unsigned a[2][4];
#pragma unroll
            for (int mt = 0; mt < 2; mt++) {
                const int r0 = wm * 32 + mt * 16 + lq;
                a[mt][0] = __float_as_uint(Qs[r0 * 68 + k + lr]);
                a[mt][1] = __float_as_uint(Qs[(r0 + 8) * 68 + k + lr]);
                a[mt][2] = __float_as_uint(Qs[r0 * 68 + k + 4 + lr]);
                a[mt][3] = __float_as_uint(Qs[(r0 + 8) * 68 + k + 4 + lr]);
            }
#pragma unroll
            for (int nt = 0; nt < 8; nt++) {
                const int nc = wn * 64 + nt * 8 + lq;
                const unsigned b0 = __float_as_uint(Ks[nc * 68 + k + lr]);
                const unsigned b1 = __float_as_uint(Ks[nc * 68 + k + 4 + lr]);
                mma8(acc[0][nt], a[0][0], a[0][1], a[0][2], a[0][3], b0, b1);
                mma8(acc[1][nt], a[1][0], a[1][1], a[1][2], a[1][3], b0, b1);
            }
        }

        // ---- exp, rowsum, write unnormalized attn + stage P ----
#pragma unroll
        for (int mt = 0; mt < 2; mt++) {
            const int r0 = wm * 32 + mt * 16 + lq;
#pragma unroll
            for (int nt = 0; nt < 8; nt++) {
                const float p0 = __expf(acc[mt][nt][0] * INV_SCALE);
                const float p1 = __expf(acc[mt][nt][1] * INV_SCALE);
                const float p2 = __expf(acc[mt][nt][2] * INV_SCALE);
                const float p3 = __expf(acc[mt][nt][3] * INV_SCALE);
                rs[mt * 2 + 0] += p0 + p1;
                rs[mt * 2 + 1] += p2 + p3;
                const int col = wn * 64 + nt * 8 + 2 * lr;
                *(float2*)(attn_base + (size_t)r0 * L_ + kt * 128 + col) =
                    make_float2(p0, p1);
                *(float2*)(attn_base + (size_t)(r0 + 8) * L_ + kt * 128 + col) =
                    make_float2(p2, p3);
                *(float2*)(Ps + r0 * 132 + col) = make_float2(f2tf(p0), f2tf(p1));
                *(float2*)(Ps + (r0 + 8) * 132 + col) = make_float2(f2tf(p2), f2tf(p3));
            }
        }
        __syncthreads();

        // ---- Y += P V : warp w owns rows [16w,16w+16), k over 128 keys ----
#pragma unroll
        for (int ks = 0; ks < 16; ks++) {
            const int k = ks * 8;
            const int r0 = wid * 16 + lq;
            const unsigned a0 = __float_as_uint(Ps[r0 * 132 + k + lr]);
            const unsigned a1 = __float_as_uint(Ps[(r0 + 8) * 132 + k + lr]);
            const unsigned a2 = __float_as_uint(Ps[r0 * 132 + k + 4 + lr]);
            const unsigned a3 = __float_as_uint(Ps[(r0 + 8) * 132 + k + 4 + lr]);
#pragma unroll
            for (int nt = 0; nt < 8; nt++) {
                const int d = nt * 8 + lq;
                const unsigned b0 = __float_as_uint(Vs[(k + lr) * 68 + d]);
                const unsigned b1 = __float_as_uint(Vs[(k + 4 + lr) * 68 + d]);
                mma8(accY[nt], a0, a1, a2, a3, b0, b1);
            }
        }
    }

    // ---- row sums: reduce over quad (lane&3), combine col-halves ----
#pragma unroll
    for (int i = 0; i < 4; i++) {
        rs[i] += __shfl_xor_sync(0xffffffff, rs[i], 1);
        rs[i] += __shfl_xor_sync(0xffffffff, rs[i], 2);
    }
    if (lr == 0) {
#pragma unroll
        for (int i = 0; i < 4; i++) {
            const int row = wm * 32 + (i >> 1) * 16 + (i & 1) * 8 + lq;
            red[wn * 128 + row] = rs[i];
        }
    }
    __syncthreads();
    if (t < 128) {
        const float inv = 1.0f / (red[t] + red[128 + t]);
        rsi[t] = inv;
        g_RSinv[bh * L_ + qt * 128 + t] = inv;
    }
    __syncthreads();

    // ---- normalize Y, store concatenated-head layout ----
    {
        const int b = bh >> 4, h = bh & 15;
        const int r0 = wid * 16 + lq;
        const float inv0 = rsi[r0], inv1 = rsi[r0 + 8];
        const int grow0 = b * L_ + qt * 128 + r0;
#pragma unroll
        for (int nt = 0; nt < 8; nt++) {
            const int d = nt * 8 + 2 * lr;
            *(float2*)(g_YH + (size_t)grow0 * C_ + h * 64 + d) =
                make_float2(accY[nt][0] * inv0, accY[nt][1] * inv0);
            *(float2*)(g_YH + (size_t)(grow0 + 8) * C_ + h * 64 + d) =
                make_float2(accY[nt][2] * inv1, accY[nt][3] * inv1);
        }
    }
}

// ---------------------------------------------------------------------------
// Normalize attn in place: attn *= 1/rowsum
// ---------------------------------------------------------------------------
__global__ void attn_norm(float4* __restrict__ attn, const float* __restrict__ rsi)
{
    size_t i = (size_t)blockIdx.x * blockDim.x + threadIdx.x;
    const float r = rsi[i >> 9];
    float4 v = attn[i];
    v.x *= r; v.y *= r; v.z *= r; v.w *= r;
    attn[i] = v;
}

// ---------------------------------------------------------------------------
// kernel_launch
// ---------------------------------------------------------------------------
extern "C" void kernel_launch(void* const* d_in, const int* in_sizes, int n_in,
                              void* d_out, int out_size)
{
    const float* q    = (const float*)d_in[0];
    const float* k    = (const float*)d_in[1];
    const float* v    = (const float*)d_in[2];
    const float* w_q  = (const float*)d_in[3];
    const float* w_k  = (const float*)d_in[4];
    const float* w_v  = (const float*)d_in[5];
    const float* fc_y = (const float*)d_in[6];

    float* y_out    = (float*)d_out;
    float* attn_out = y_out + Y_ELEMS;

    float *pQH, *pKH, *pVH, *pYH, *pRS;
    cudaGetSymbolAddress((void**)&pQH, g_QH);
    cudaGetSymbolAddress((void**)&pKH, g_KH);
    cudaGetSymbolAddress((void**)&pVH, g_VH);
    cudaGetSymbolAddress((void**)&pYH, g_YH);
    cudaGetSymbolAddress((void**)&pRS, g_RSinv);

    dim3 gGemm(C_ / 128, MTOT / 128);   // (8, 32)
    dim3 blk(256);

    // Projections -> head-major scratch (tf32 tensor cores)
    gemm_tf32<<<gGemm, blk>>>(q, w_q, pQH, 1);
    gemm_tf32<<<gGemm, blk>>>(k, w_k, pKH, 1);
    gemm_tf32<<<gGemm, blk>>>(v, w_v, pVH, 1);

    // Fused attention (unnormalized attn write + normalized Y)
    cudaFuncSetAttribute(attn_tc, cudaFuncAttributeMaxDynamicSharedMemorySize,
                         AT_BYTES);
    attn_tc<<<dim3(L_ / 128, B_ * H_), blk, AT_BYTES>>>(attn_out);

    // Normalize attn in place
    attn_norm<<<(unsigned)(ATTN_ELEMS / 4 / 256), 256>>>((float4*)attn_out, pRS);

    // y = Y @ fc_y^T
    gemm_tf32<<<gGemm, blk>>>(pYH, fc_y, y_out, 0);
}